// round 15
// baseline (speedup 1.0000x reference)
#include <cuda_runtime.h>
#include <cuda_fp16.h>
#include <math.h>

// ---------------------------------------------------------------------------
// RegionLoss (YOLO-style), fixed shapes — single fused kernel, fp16x2 IoU test,
// 4 cells/thread, 128-thread blocks (1440 desynchronized blocks, ~10/SM),
// two-ballot validity (no patch barrier), atomic loss accumulation.
//   output : (16, 75, 96, 96) f32, target: (16, 50, 7) f32, anchors: (10,) f32
// out: (loss, nCorrect, nGT) f32
// ---------------------------------------------------------------------------

#define NB   16
#define NANC 5
#define NCL  8
#define NT   50
#define NH   96
#define NW   96
#define HW   (NH * NW)            // 9216
#define CELLS_PER_B (NANC * HW)   // 46080
#define BLKS_PER_B 90             // 46080 / (128 threads * 4 cells)
#define NBLK (NB * BLKS_PER_B)    // 1440
#define CELLS_PER_BLK 512

#define THRESH_Q 0.375f           // iou>0.6 <=> inter > 0.375*(areaP+areaG)

typedef unsigned int uint;

__device__ __forceinline__ uint h2u(__half2 h) { return *(uint*)&h; }
__device__ __forceinline__ __half2 u2h(uint u) { return *(__half2*)&u; }

// -------------------- device scratch (no allocations allowed) ---------------
__device__ float g_accF;          // persistent accumulators; last block resets
__device__ int   g_accGT, g_accCC;
__device__ int   g_ticket;        // monotonic; (old+1)%NBLK==0 -> last block

__device__ __forceinline__ float sig_fast(float x) { return 1.0f / (1.0f + __expf(-x)); }
__device__ __forceinline__ float sig_acc(float x)  { return 1.0f / (1.0f + expf(-x)); }

// -------------------- the one kernel ----------------------------------------
// grid = (90, 16), block = 128, 4 cells/thread as 2 half2 units
__global__ void __launch_bounds__(128, 10)
k_all(const float* __restrict__ out, const float* __restrict__ tgt,
      const float* __restrict__ anc, float* __restrict__ o, int n) {
    const int b     = blockIdx.y;
    const int blk   = blockIdx.x;
    const int tid   = threadIdx.x;
    const int lane  = tid & 31;
    const int warp  = tid >> 5;
    const int cell0 = blk * CELLS_PER_BLK;

    __shared__ float         s_tgt[NT * 7];
    __shared__ __align__(16) uint s_bp[NT][8];  // {xlo2,xhi2,ylo2,yhi2,mth2,...}
    __shared__ int           s_idx[NT];
    __shared__ unsigned char s_flags[NT];       // bit0 valid, bit1 winner(in-window)
    __shared__ __align__(16) uint s_matchw[CELLS_PER_BLK / 4];
    __shared__ int           s_cnt[2];
    __shared__ float         s_redf[4];
    __shared__ int           s_last;

    // ---- main per-cell global loads first (longest latency, overlap prep) ----
    const int u   = cell0 + tid * 4;           // 4-cell group, never crosses a row
    const int a   = u / HW;
    const int rem = u - a * HW;
    const int h   = rem / NW;
    const int w0  = rem - h * NW;
    const float* base = out + (size_t)(b * 75 + a * 15) * HW + rem;

    const float4 xr  = *(const float4*)(base);
    const float4 yr  = *(const float4*)(base + HW);
    const float4 wr  = *(const float4*)(base + 2 * HW);
    const float4 lr  = *(const float4*)(base + 3 * HW);
    const float4 cfr = *(const float4*)(base + 6 * HW);

    // ---- phase A: stage targets, zero match map ------------------------------
    for (int i = tid; i < NT * 7; i += 128) s_tgt[i] = tgt[b * NT * 7 + i];
    s_matchw[tid] = 0u;                        // 128 words exactly
    if (tid < 2) s_cnt[tid] = 0;
    __syncthreads();

    // ---- prep (warps 0-1): two-ballot validity, packed fp16 boxes -------------
    if (warp < 2) {
        // every prep warp computes the targets-0..31 validity mask itself
        float v0 = s_tgt[lane * 7 + 1];
        uint mA = __ballot_sync(0xffffffffu, v0 != 0.0f);
        uint mB = 0u;
        if (warp == 1) {
            int t2 = 32 + lane;
            float v1 = (t2 < NT) ? s_tgt[t2 * 7 + 1] : 1.0f;
            mB = __ballot_sync(0xffffffffu, v1 != 0.0f);
        }
        const int t = warp * 32 + lane;
        if (t < NT) {
            bool valid;
            if (warp == 0) valid = (((~mA) & ((2u << lane) - 1u)) == 0u);
            else           valid = (mA == 0xffffffffu) &&
                                   (((~mB) & ((2u << lane) - 1u)) == 0u);

            float gx = s_tgt[t * 7 + 1] * (float)NW;
            float gy = s_tgt[t * 7 + 2] * (float)NH;
            float gw = s_tgt[t * 7 + 3] * (float)NW;
            float gl = s_tgt[t * 7 + 4] * (float)NH;

            int bn = 0;
            float best = -1.0f;
            #pragma unroll
            for (int i = 0; i < NANC; i++) {
                float aw2 = __ldg(anc + 2 * i);
                float ah2 = __ldg(anc + 2 * i + 1);
                float inter = fminf(gw, aw2) * fminf(gl, ah2);
                float iou = inter / ((gw * gl + aw2 * ah2) - inter);
                if (iou > best) { best = iou; bn = i; }
            }
            int gi = min(max((int)gx, 0), NW - 1);
            int gj = min(max((int)gy, 0), NH - 1);
            int idxl = (bn * NH + gj) * NW + gi;

            if (valid) {
                s_idx[t] = idxl;
                s_bp[t][0] = h2u(__float2half2_rn(gx - 0.5f * gw));
                s_bp[t][1] = h2u(__float2half2_rn(gx + 0.5f * gw));
                s_bp[t][2] = h2u(__float2half2_rn(gy - 0.5f * gl));
                s_bp[t][3] = h2u(__float2half2_rn(gy + 0.5f * gl));
                s_bp[t][4] = h2u(__float2half2_rn(-THRESH_Q * gw * gl));
                s_flags[t] = 1u;
            } else {
                s_idx[t] = -2 - t;
                // sentinel: cw clamps to 0, ch FINITE (no 0*inf NaN), mth huge-neg
                s_bp[t][0] = h2u(__float2half2_rn( 60000.f));
                s_bp[t][1] = h2u(__float2half2_rn(-60000.f));
                s_bp[t][2] = h2u(__float2half2_rn(0.f));
                s_bp[t][3] = h2u(__float2half2_rn(0.f));
                s_bp[t][4] = h2u(__float2half2_rn(-60000.f));
                s_flags[t] = 0u;
            }
        }
    }

    // ---- per-cell geometry (all warps; overlaps prep for warps 2-3) -----------
    const float X[4] = {xr.x, xr.y, xr.z, xr.w};
    const float Y[4] = {yr.x, yr.y, yr.z, yr.w};
    const float W[4] = {wr.x, wr.y, wr.z, wr.w};
    const float L[4] = {lr.x, lr.y, lr.z, lr.w};

    const float caw = __ldg(anc + 2 * a);
    const float cah = __ldg(anc + 2 * a + 1);

    __half2 xlo2[2], xhi2[2], ylo2[2], yhi2[2], accE[2], accO[2];
    float nap[4];
    #pragma unroll
    for (int i = 0; i < 2; i++) {
        float xl[2], xh[2], yl[2], yh[2];
        #pragma unroll
        for (int k = 0; k < 2; k++) {
            int c = 2 * i + k;
            float sx  = sig_fast(X[c]);
            float sy  = sig_fast(Y[c]);
            float pw  = __expf(W[c]) * caw;
            float pl  = __expf(L[c]) * cah;
            float px  = sx + (float)(w0 + c);
            float py  = sy + (float)h;
            xl[k] = px - 0.5f * pw;  xh[k] = px + 0.5f * pw;
            yl[k] = py - 0.5f * pl;  yh[k] = py + 0.5f * pl;
            nap[c] = -THRESH_Q * pw * pl;
        }
        xlo2[i] = __floats2half2_rn(xl[0], xl[1]);
        xhi2[i] = __floats2half2_rn(xh[0], xh[1]);
        ylo2[i] = __floats2half2_rn(yl[0], yl[1]);
        yhi2[i] = __floats2half2_rn(yh[0], yh[1]);
        accE[i] = __float2half2_rn(-60000.f);
        accO[i] = accE[i];
    }
    const __half2 z2 = __float2half2_rn(0.f);

    __syncthreads();

    // ---- winner + match-map write + phase-C L1 prefetch ------------------------
    if (tid < NT && (s_flags[tid] & 1u)) {
        int idxl = s_idx[tid];
        if (idxl >= cell0 && idxl < cell0 + CELLS_PER_BLK) {
            bool winner = true;
            for (int t2 = tid + 1; t2 < NT; t2++)
                if (s_idx[t2] == idxl) winner = false;
            if (winner) {
                s_flags[tid] = 3u;
                ((unsigned char*)s_matchw)[idxl - cell0] = (unsigned char)(tid + 1);
            }
            int bn = idxl / HW;
            int r2 = idxl - bn * HW;
            const float* cbp = out + (size_t)(b * 75 + bn * 15) * HW + r2;
            #pragma unroll
            for (int c = 0; c < 15; c++)
                asm volatile("prefetch.global.L1 [%0];" :: "l"(cbp + c * HW));
        }
    }
    __syncthreads();

    // ---- main IoU loop: 9 half2 ops per unit per target, even/odd acc ----------
    #pragma unroll 10
    for (int t = 0; t < NT; t += 2) {
        {
            const uint4 q = *(const uint4*)&s_bp[t][0];
            const __half2 Bxlo = u2h(q.x), Bxhi = u2h(q.y);
            const __half2 Bylo = u2h(q.z), Byhi = u2h(q.w);
            const __half2 Bmth = u2h(s_bp[t][4]);
            #pragma unroll
            for (int i = 0; i < 2; i++) {
                __half2 cw = __hmax2(__hsub2(__hmin2(xhi2[i], Bxhi),
                                             __hmax2(xlo2[i], Bxlo)), z2);
                __half2 ch = __hsub2(__hmin2(yhi2[i], Byhi),
                                     __hmax2(ylo2[i], Bylo));
                accE[i] = __hmax2(accE[i], __hfma2(cw, ch, Bmth));
            }
        }
        {
            const uint4 q = *(const uint4*)&s_bp[t + 1][0];
            const __half2 Bxlo = u2h(q.x), Bxhi = u2h(q.y);
            const __half2 Bylo = u2h(q.z), Byhi = u2h(q.w);
            const __half2 Bmth = u2h(s_bp[t + 1][4]);
            #pragma unroll
            for (int i = 0; i < 2; i++) {
                __half2 cw = __hmax2(__hsub2(__hmin2(xhi2[i], Bxhi),
                                             __hmax2(xlo2[i], Bxlo)), z2);
                __half2 ch = __hsub2(__hmin2(yhi2[i], Byhi),
                                     __hmax2(ylo2[i], Bylo));
                accO[i] = __hmax2(accO[i], __hfma2(cw, ch, Bmth));
            }
        }
    }

    bool F[4];
    #pragma unroll
    for (int i = 0; i < 2; i++) {
        __half2 acc = __hmax2(accE[i], accO[i]);
        F[2 * i]     = __low2float(acc)  + nap[2 * i]     > 0.0f;
        F[2 * i + 1] = __high2float(acc) + nap[2 * i + 1] > 0.0f;
    }

    // ---- no-obj conf terms (matched cells handled in phase C) ------------------
    const uint mkw = s_matchw[tid];
    const float CF[4] = {cfr.x, cfr.y, cfr.z, cfr.w};

    float part = 0.0f;
    #pragma unroll
    for (int c = 0; c < 4; c++) {
        uint mk = (mkw >> (8 * c)) & 0xffu;
        if (mk == 0u && !F[c]) {
            float cf = sig_fast(CF[c]);
            part += cf * cf;
        }
    }

    // ---- phase C: targets owned by this block (exact fp32 reference math) ------
    if (tid < NT && (s_flags[tid] & 1u)) {
        int idxl = s_idx[tid];
        if (idxl >= cell0 && idxl < cell0 + CELLS_PER_BLK) {
            float gx = s_tgt[tid * 7 + 1] * (float)NW;
            float gy = s_tgt[tid * 7 + 2] * (float)NH;
            float gw = s_tgt[tid * 7 + 3] * (float)NW;
            float gl = s_tgt[tid * 7 + 4] * (float)NH;

            int bn = 0;
            float best = -1.0f;
            #pragma unroll
            for (int i = 0; i < NANC; i++) {
                float aw2 = __ldg(anc + 2 * i);
                float ah2 = __ldg(anc + 2 * i + 1);
                float inter = fminf(gw, aw2) * fminf(gl, ah2);
                float iou = inter / ((gw * gl + aw2 * ah2) - inter);
                if (iou > best) { best = iou; bn = i; }
            }
            float aw_ = __ldg(anc + 2 * bn);
            float ah_ = __ldg(anc + 2 * bn + 1);
            int gi = min(max((int)gx, 0), NW - 1);
            int gj = min(max((int)gy, 0), NH - 1);

            const float* cb = out + (size_t)(b * 75 + bn * 15) * HW + (size_t)gj * NW + gi;
            float xr0 = cb[0], yr0 = cb[HW], wr0 = cb[2 * HW], lr0 = cb[3 * HW];
            float sx = sig_acc(xr0);
            float sy = sig_acc(yr0);
            float px = sx + (float)gi;
            float py = sy + (float)gj;
            float pw = expf(wr0) * aw_;
            float pl = expf(lr0) * ah_;

            float mx = fminf(px - pw * 0.5f, gx - gw * 0.5f);
            float Mx = fmaxf(px + pw * 0.5f, gx + gw * 0.5f);
            float my = fminf(py - pl * 0.5f, gy - gl * 0.5f);
            float My = fmaxf(py + pl * 0.5f, gy + gl * 0.5f);
            float cw = (pw + gw) - (Mx - mx);
            float ch = (pl + gl) - (My - my);
            float inter = ((cw > 0.f) && (ch > 0.f)) ? (cw * ch) : 0.0f;
            float iou = inter / ((pw * pl + gw * gl) - inter);

            atomicAdd(&s_cnt[0], 1);
            if (iou > 0.5f) atomicAdd(&s_cnt[1], 1);

            if (s_flags[tid] & 2u) {   // winner
                float dx = sx - (gx - (float)gi);
                float dy = sy - (gy - (float)gj);
                float dw = wr0 - logf(gw / aw_);
                float dl = lr0 - logf(gl / ah_);
                float di = cb[4 * HW] - s_tgt[tid * 7 + 5];
                float dr = cb[5 * HW] - s_tgt[tid * 7 + 6];
                float cf = sig_acc(cb[6 * HW]);
                float dc = cf - iou;

                float lg[NCL];
                #pragma unroll
                for (int c = 0; c < NCL; c++) lg[c] = cb[(7 + c) * HW];
                float m2 = lg[0];
                #pragma unroll
                for (int c = 1; c < NCL; c++) m2 = fmaxf(m2, lg[c]);
                float s = 0.f;
                #pragma unroll
                for (int c = 0; c < NCL; c++) s += expf(lg[c] - m2);
                int tcls = (int)s_tgt[tid * 7 + 0];
                float ce = (m2 + logf(s)) - lg[tcls];

                part += dx * dx + dy * dy + dw * dw + dl * dl + di * di + dr * dr
                      + 100.0f * dc * dc + ce;
            }
        }
    }

    // ---- block reduction + atomic accumulate -------------------------------------
    #pragma unroll
    for (int off = 16; off > 0; off >>= 1)
        part += __shfl_down_sync(0xffffffffu, part, off);
    if (lane == 0) s_redf[warp] = part;
    __syncthreads();

    if (tid == 0) {
        float v = s_redf[0] + s_redf[1] + s_redf[2] + s_redf[3];
        atomicAdd(&g_accF, v);
        if (s_cnt[0]) {
            atomicAdd(&g_accGT, s_cnt[0]);
            if (s_cnt[1]) atomicAdd(&g_accCC, s_cnt[1]);
        }
        __threadfence();
        int old = atomicAdd(&g_ticket, 1);
        s_last = (((old + 1) % NBLK) == 0) ? 1 : 0;
    }
    __syncthreads();

    // ---- last block finalizes: copy 3 scalars, reset accumulators ----------------
    if (s_last) {
        if (tid == 0) {
            float lv = __ldcg(&g_accF);
            int   gt = __ldcg(&g_accGT);
            int   cc = __ldcg(&g_accCC);
            if (n > 0) o[0] = lv;
            if (n > 1) o[1] = (float)cc;
            if (n > 2) o[2] = (float)gt;
            g_accF  = 0.0f;      // reset for next (replayed) launch
            g_accGT = 0;
            g_accCC = 0;
            __threadfence();
        }
        for (int k = 3 + tid; k < n; k += 128) o[k] = 0.0f;
    }
}

// -------------------- launch --------------------------------------------------
extern "C" void kernel_launch(void* const* d_in, const int* in_sizes, int n_in,
                              void* d_out, int out_size) {
    const float* output  = (const float*)d_in[0];
    const float* target  = (const float*)d_in[1];
    const float* anchors = (const float*)d_in[2];

    k_all<<<dim3(BLKS_PER_B, NB), 128>>>(output, target, anchors,
                                         (float*)d_out, out_size);
}

// round 16
// speedup vs baseline: 1.0811x; 1.0811x over previous
#include <cuda_runtime.h>
#include <cuda_fp16.h>
#include <math.h>

// ---------------------------------------------------------------------------
// RegionLoss (YOLO-style), fixed shapes — single fused kernel, fp16x2 IoU test,
// 4 cells/thread, 256-thread blocks, lean prep (2 barriers, no staging,
// division-free argmax), atomic loss accumulation.
//   output : (16, 75, 96, 96) f32, target: (16, 50, 7) f32, anchors: (10,) f32
// out: (loss, nCorrect, nGT) f32
// ---------------------------------------------------------------------------

#define NB   16
#define NANC 5
#define NCL  8
#define NT   50
#define NH   96
#define NW   96
#define HW   (NH * NW)            // 9216
#define CELLS_PER_B (NANC * HW)   // 46080
#define BLKS_PER_B 45             // 46080 / (256 threads * 4 cells)
#define NBLK (NB * BLKS_PER_B)    // 720
#define CELLS_PER_BLK 1024

#define THRESH_Q 0.375f           // iou>0.6 <=> inter > 0.375*(areaP+areaG)

typedef unsigned int uint;

__device__ __forceinline__ uint h2u(__half2 h) { return *(uint*)&h; }
__device__ __forceinline__ __half2 u2h(uint u) { return *(__half2*)&u; }

// -------------------- device scratch (no allocations allowed) ---------------
__device__ float g_accF;          // persistent accumulators; last block resets
__device__ int   g_accGT, g_accCC;
__device__ int   g_ticket;        // monotonic; (old+1)%NBLK==0 -> last block

__device__ __forceinline__ float sig_fast(float x) { return 1.0f / (1.0f + __expf(-x)); }
__device__ __forceinline__ float sig_acc(float x)  { return 1.0f / (1.0f + expf(-x)); }

// division-free argmax over anchors: iou_i > iou_best  <=>  inter_i*den_best >
// inter_best*den_i  (all terms positive). Strict '>' keeps first-wins ties,
// matching the reference argmax.
__device__ __forceinline__ int best_anchor(float gw, float gl,
                                           const float* __restrict__ anc) {
    float area = gw * gl;
    int   bn = 0;
    float bi, bd;
    {
        float aw_ = __ldg(anc), ah_ = __ldg(anc + 1);
        bi = fminf(gw, aw_) * fminf(gl, ah_);
        bd = (area + aw_ * ah_) - bi;
    }
    #pragma unroll
    for (int i = 1; i < NANC; i++) {
        float aw_ = __ldg(anc + 2 * i), ah_ = __ldg(anc + 2 * i + 1);
        float ii = fminf(gw, aw_) * fminf(gl, ah_);
        float di = (area + aw_ * ah_) - ii;
        if (ii * bd > bi * di) { bi = ii; bd = di; bn = i; }
    }
    return bn;
}

// -------------------- the one kernel ----------------------------------------
// grid = (45, 16), block = 256, 4 cells/thread as 2 half2 units
__global__ void __launch_bounds__(256, 5)
k_all(const float* __restrict__ out, const float* __restrict__ tgt,
      const float* __restrict__ anc, float* __restrict__ o, int n) {
    const int b     = blockIdx.y;
    const int blk   = blockIdx.x;
    const int tid   = threadIdx.x;
    const int lane  = tid & 31;
    const int warp  = tid >> 5;
    const int cell0 = blk * CELLS_PER_BLK;

    __shared__ __align__(16) uint s_bp[NT][8];  // {xlo2,xhi2,ylo2,yhi2,mth2,...}
    __shared__ int           s_idx[NT];
    __shared__ unsigned char s_flags[NT];       // bit0 valid, bit1 winner(in-window)
    __shared__ __align__(16) uint s_matchw[CELLS_PER_BLK / 4];
    __shared__ int           s_cnt[2];
    __shared__ float         s_redf[8];
    __shared__ int           s_last;

    // ---- main per-cell global loads first (longest latency, overlap prep) ----
    const int u   = cell0 + tid * 4;           // 4-cell group, never crosses a row
    const int a   = u / HW;
    const int rem = u - a * HW;
    const int h   = rem / NW;
    const int w0  = rem - h * NW;
    const float* base = out + (size_t)(b * 75 + a * 15) * HW + rem;

    const float4 xr  = *(const float4*)(base);
    const float4 yr  = *(const float4*)(base + HW);
    const float4 wr  = *(const float4*)(base + 2 * HW);
    const float4 lr  = *(const float4*)(base + 3 * HW);
    const float4 cfr = *(const float4*)(base + 6 * HW);

    // ---- zero match map / counters (no target staging pass) -------------------
    s_matchw[tid] = 0u;
    if (tid < 2) s_cnt[tid] = 0;

    // ---- prep (warps 0-1): direct-LDG targets, two-ballot validity ------------
    if (warp < 2) {
        // each prep warp re-derives warp0's validity column itself
        float v0 = __ldg(tgt + (b * NT + lane) * 7 + 1);
        uint mA = __ballot_sync(0xffffffffu, v0 != 0.0f);
        uint mB = 0u;
        if (warp == 1) {
            int t2 = 32 + lane;
            float v1 = (t2 < NT) ? __ldg(tgt + (b * NT + t2) * 7 + 1) : 1.0f;
            mB = __ballot_sync(0xffffffffu, v1 != 0.0f);
        }
        const int t = warp * 32 + lane;
        if (t < NT) {
            bool valid;
            if (warp == 0) valid = (((~mA) & ((2u << lane) - 1u)) == 0u);
            else           valid = (mA == 0xffffffffu) &&
                                   (((~mB) & ((2u << lane) - 1u)) == 0u);

            const float* tp = tgt + (b * NT + t) * 7;
            float gx = __ldg(tp + 1) * (float)NW;
            float gy = __ldg(tp + 2) * (float)NH;
            float gw = __ldg(tp + 3) * (float)NW;
            float gl = __ldg(tp + 4) * (float)NH;

            int bn = best_anchor(gw, gl, anc);
            int gi = min(max((int)gx, 0), NW - 1);
            int gj = min(max((int)gy, 0), NH - 1);
            int idxl = (bn * NH + gj) * NW + gi;

            if (valid) {
                s_idx[t] = idxl;
                s_bp[t][0] = h2u(__float2half2_rn(gx - 0.5f * gw));
                s_bp[t][1] = h2u(__float2half2_rn(gx + 0.5f * gw));
                s_bp[t][2] = h2u(__float2half2_rn(gy - 0.5f * gl));
                s_bp[t][3] = h2u(__float2half2_rn(gy + 0.5f * gl));
                s_bp[t][4] = h2u(__float2half2_rn(-THRESH_Q * gw * gl));
                s_flags[t] = 1u;
            } else {
                s_idx[t] = -2 - t;
                // sentinel: cw clamps to 0, ch FINITE (no 0*inf NaN), mth huge-neg
                s_bp[t][0] = h2u(__float2half2_rn( 60000.f));
                s_bp[t][1] = h2u(__float2half2_rn(-60000.f));
                s_bp[t][2] = h2u(__float2half2_rn(0.f));
                s_bp[t][3] = h2u(__float2half2_rn(0.f));
                s_bp[t][4] = h2u(__float2half2_rn(-60000.f));
                s_flags[t] = 0u;
            }
        }
    }
    __syncthreads();   // barrier 1: boxes/idx/flags + matchw-zero complete

    // ---- winner + match-map write + phase-C L1 prefetch ------------------------
    if (tid < NT && (s_flags[tid] & 1u)) {
        int idxl = s_idx[tid];
        if (idxl >= cell0 && idxl < cell0 + CELLS_PER_BLK) {
            bool winner = true;
            for (int t2 = tid + 1; t2 < NT; t2++)
                if (s_idx[t2] == idxl) winner = false;
            if (winner) {
                s_flags[tid] = 3u;
                ((unsigned char*)s_matchw)[idxl - cell0] = (unsigned char)(tid + 1);
            }
            int bn = idxl / HW;
            int r2 = idxl - bn * HW;
            const float* cbp = out + (size_t)(b * 75 + bn * 15) * HW + r2;
            #pragma unroll
            for (int c = 0; c < 15; c++)
                asm volatile("prefetch.global.L1 [%0];" :: "l"(cbp + c * HW));
        }
    }

    // ---- per-cell geometry (overlaps winner pass for non-prep threads) ---------
    const float X[4] = {xr.x, xr.y, xr.z, xr.w};
    const float Y[4] = {yr.x, yr.y, yr.z, yr.w};
    const float W[4] = {wr.x, wr.y, wr.z, wr.w};
    const float L[4] = {lr.x, lr.y, lr.z, lr.w};

    const float caw = __ldg(anc + 2 * a);
    const float cah = __ldg(anc + 2 * a + 1);

    __half2 xlo2[2], xhi2[2], ylo2[2], yhi2[2], accE[2], accO[2];
    float nap[4];
    #pragma unroll
    for (int i = 0; i < 2; i++) {
        float xl[2], xh[2], yl[2], yh[2];
        #pragma unroll
        for (int k = 0; k < 2; k++) {
            int c = 2 * i + k;
            float sx  = sig_fast(X[c]);
            float sy  = sig_fast(Y[c]);
            float pw  = __expf(W[c]) * caw;
            float pl  = __expf(L[c]) * cah;
            float px  = sx + (float)(w0 + c);
            float py  = sy + (float)h;
            xl[k] = px - 0.5f * pw;  xh[k] = px + 0.5f * pw;
            yl[k] = py - 0.5f * pl;  yh[k] = py + 0.5f * pl;
            nap[c] = -THRESH_Q * pw * pl;
        }
        xlo2[i] = __floats2half2_rn(xl[0], xl[1]);
        xhi2[i] = __floats2half2_rn(xh[0], xh[1]);
        ylo2[i] = __floats2half2_rn(yl[0], yl[1]);
        yhi2[i] = __floats2half2_rn(yh[0], yh[1]);
        accE[i] = __float2half2_rn(-60000.f);
        accO[i] = accE[i];
    }
    const __half2 z2 = __float2half2_rn(0.f);

    __syncthreads();   // barrier 2: match map final

    // ---- main IoU loop: 9 half2 ops per unit per target, even/odd acc ----------
    #pragma unroll 10
    for (int t = 0; t < NT; t += 2) {
        {
            const uint4 q = *(const uint4*)&s_bp[t][0];
            const __half2 Bxlo = u2h(q.x), Bxhi = u2h(q.y);
            const __half2 Bylo = u2h(q.z), Byhi = u2h(q.w);
            const __half2 Bmth = u2h(s_bp[t][4]);
            #pragma unroll
            for (int i = 0; i < 2; i++) {
                __half2 cw = __hmax2(__hsub2(__hmin2(xhi2[i], Bxhi),
                                             __hmax2(xlo2[i], Bxlo)), z2);
                __half2 ch = __hsub2(__hmin2(yhi2[i], Byhi),
                                     __hmax2(ylo2[i], Bylo));
                accE[i] = __hmax2(accE[i], __hfma2(cw, ch, Bmth));
            }
        }
        {
            const uint4 q = *(const uint4*)&s_bp[t + 1][0];
            const __half2 Bxlo = u2h(q.x), Bxhi = u2h(q.y);
            const __half2 Bylo = u2h(q.z), Byhi = u2h(q.w);
            const __half2 Bmth = u2h(s_bp[t + 1][4]);
            #pragma unroll
            for (int i = 0; i < 2; i++) {
                __half2 cw = __hmax2(__hsub2(__hmin2(xhi2[i], Bxhi),
                                             __hmax2(xlo2[i], Bxlo)), z2);
                __half2 ch = __hsub2(__hmin2(yhi2[i], Byhi),
                                     __hmax2(ylo2[i], Bylo));
                accO[i] = __hmax2(accO[i], __hfma2(cw, ch, Bmth));
            }
        }
    }

    bool F[4];
    #pragma unroll
    for (int i = 0; i < 2; i++) {
        __half2 acc = __hmax2(accE[i], accO[i]);
        F[2 * i]     = __low2float(acc)  + nap[2 * i]     > 0.0f;
        F[2 * i + 1] = __high2float(acc) + nap[2 * i + 1] > 0.0f;
    }

    // ---- no-obj conf terms (matched cells handled in phase C) ------------------
    const uint mkw = s_matchw[tid];
    const float CF[4] = {cfr.x, cfr.y, cfr.z, cfr.w};

    float part = 0.0f;
    #pragma unroll
    for (int c = 0; c < 4; c++) {
        uint mk = (mkw >> (8 * c)) & 0xffu;
        if (mk == 0u && !F[c]) {
            float cf = sig_fast(CF[c]);
            part += cf * cf;
        }
    }

    // ---- phase C: targets owned by this block (exact fp32 reference math) ------
    if (tid < NT && (s_flags[tid] & 1u)) {
        int idxl = s_idx[tid];
        if (idxl >= cell0 && idxl < cell0 + CELLS_PER_BLK) {
            const float* tp = tgt + (b * NT + tid) * 7;
            float gx = __ldg(tp + 1) * (float)NW;
            float gy = __ldg(tp + 2) * (float)NH;
            float gw = __ldg(tp + 3) * (float)NW;
            float gl = __ldg(tp + 4) * (float)NH;

            int bn = best_anchor(gw, gl, anc);   // same decision as prep
            float aw_ = __ldg(anc + 2 * bn);
            float ah_ = __ldg(anc + 2 * bn + 1);
            int gi = min(max((int)gx, 0), NW - 1);
            int gj = min(max((int)gy, 0), NH - 1);

            const float* cb = out + (size_t)(b * 75 + bn * 15) * HW + (size_t)gj * NW + gi;
            float xr0 = cb[0], yr0 = cb[HW], wr0 = cb[2 * HW], lr0 = cb[3 * HW];
            float sx = sig_acc(xr0);
            float sy = sig_acc(yr0);
            float px = sx + (float)gi;
            float py = sy + (float)gj;
            float pw = expf(wr0) * aw_;
            float pl = expf(lr0) * ah_;

            float mx = fminf(px - pw * 0.5f, gx - gw * 0.5f);
            float Mx = fmaxf(px + pw * 0.5f, gx + gw * 0.5f);
            float my = fminf(py - pl * 0.5f, gy - gl * 0.5f);
            float My = fmaxf(py + pl * 0.5f, gy + gl * 0.5f);
            float cw = (pw + gw) - (Mx - mx);
            float ch = (pl + gl) - (My - my);
            float inter = ((cw > 0.f) && (ch > 0.f)) ? (cw * ch) : 0.0f;
            float iou = inter / ((pw * pl + gw * gl) - inter);

            atomicAdd(&s_cnt[0], 1);
            if (iou > 0.5f) atomicAdd(&s_cnt[1], 1);

            if (s_flags[tid] & 2u) {   // winner
                float dx = sx - (gx - (float)gi);
                float dy = sy - (gy - (float)gj);
                float dw = wr0 - logf(gw / aw_);
                float dl = lr0 - logf(gl / ah_);
                float di = cb[4 * HW] - __ldg(tp + 5);
                float dr = cb[5 * HW] - __ldg(tp + 6);
                float cf = sig_acc(cb[6 * HW]);
                float dc = cf - iou;

                float lg[NCL];
                #pragma unroll
                for (int c = 0; c < NCL; c++) lg[c] = cb[(7 + c) * HW];
                float m2 = lg[0];
                #pragma unroll
                for (int c = 1; c < NCL; c++) m2 = fmaxf(m2, lg[c]);
                float s = 0.f;
                #pragma unroll
                for (int c = 0; c < NCL; c++) s += expf(lg[c] - m2);
                int tcls = (int)__ldg(tp + 0);
                float ce = (m2 + logf(s)) - lg[tcls];

                part += dx * dx + dy * dy + dw * dw + dl * dl + di * di + dr * dr
                      + 100.0f * dc * dc + ce;
            }
        }
    }

    // ---- block reduction + atomic accumulate -------------------------------------
    #pragma unroll
    for (int off = 16; off > 0; off >>= 1)
        part += __shfl_down_sync(0xffffffffu, part, off);
    if (lane == 0) s_redf[warp] = part;
    __syncthreads();

    if (tid == 0) {
        float v = 0.f;
        #pragma unroll
        for (int wv = 0; wv < 8; wv++) v += s_redf[wv];
        atomicAdd(&g_accF, v);
        if (s_cnt[0]) {
            atomicAdd(&g_accGT, s_cnt[0]);
            if (s_cnt[1]) atomicAdd(&g_accCC, s_cnt[1]);
        }
        __threadfence();
        int old = atomicAdd(&g_ticket, 1);
        s_last = (((old + 1) % NBLK) == 0) ? 1 : 0;
    }
    __syncthreads();

    // ---- last block finalizes: copy 3 scalars, reset accumulators ----------------
    if (s_last) {
        if (tid == 0) {
            float lv = __ldcg(&g_accF);
            int   gt = __ldcg(&g_accGT);
            int   cc = __ldcg(&g_accCC);
            if (n > 0) o[0] = lv;
            if (n > 1) o[1] = (float)cc;
            if (n > 2) o[2] = (float)gt;
            g_accF  = 0.0f;      // reset for next (replayed) launch
            g_accGT = 0;
            g_accCC = 0;
            __threadfence();
        }
        for (int k = 3 + tid; k < n; k += 256) o[k] = 0.0f;
    }
}

// -------------------- launch --------------------------------------------------
extern "C" void kernel_launch(void* const* d_in, const int* in_sizes, int n_in,
                              void* d_out, int out_size) {
    const float* output  = (const float*)d_in[0];
    const float* target  = (const float*)d_in[1];
    const float* anchors = (const float*)d_in[2];

    k_all<<<dim3(BLKS_PER_B, NB), 256>>>(output, target, anchors,
                                         (float*)d_out, out_size);
}

// round 17
// speedup vs baseline: 1.0845x; 1.0031x over previous
#include <cuda_runtime.h>
#include <cuda_fp16.h>
#include <math.h>

// ---------------------------------------------------------------------------
// RegionLoss (YOLO-style), fixed shapes — single fused kernel, fp16x2 IoU test,
// 4 cells/thread, 320-thread blocks (576 blocks -> 4 blocks/SM = 40 warps/SM,
// fixing the 256-thread occupancy quantization), lean prep, atomic accumulate.
//   output : (16, 75, 96, 96) f32, target: (16, 50, 7) f32, anchors: (10,) f32
// out: (loss, nCorrect, nGT) f32
// ---------------------------------------------------------------------------

#define NB   16
#define NANC 5
#define NCL  8
#define NT   50
#define NH   96
#define NW   96
#define HW   (NH * NW)            // 9216
#define CELLS_PER_B (NANC * HW)   // 46080
#define NTHR 320
#define CELLS_PER_BLK 1280        // 320 threads * 4 cells
#define BLKS_PER_B 36             // 46080 / 1280
#define NBLK (NB * BLKS_PER_B)    // 576
#define NWARPS (NTHR / 32)        // 10

#define THRESH_Q 0.375f           // iou>0.6 <=> inter > 0.375*(areaP+areaG)

typedef unsigned int uint;

__device__ __forceinline__ uint h2u(__half2 h) { return *(uint*)&h; }
__device__ __forceinline__ __half2 u2h(uint u) { return *(__half2*)&u; }

// -------------------- device scratch (no allocations allowed) ---------------
__device__ float g_accF;          // persistent accumulators; last block resets
__device__ int   g_accGT, g_accCC;
__device__ int   g_ticket;        // monotonic; (old+1)%NBLK==0 -> last block

__device__ __forceinline__ float sig_fast(float x) { return 1.0f / (1.0f + __expf(-x)); }
__device__ __forceinline__ float sig_acc(float x)  { return 1.0f / (1.0f + expf(-x)); }

// division-free argmax over anchors: iou_i > iou_best  <=>  inter_i*den_best >
// inter_best*den_i (all positive). Strict '>' keeps first-wins ties.
__device__ __forceinline__ int best_anchor(float gw, float gl,
                                           const float* __restrict__ anc) {
    float area = gw * gl;
    int   bn = 0;
    float bi, bd;
    {
        float aw_ = __ldg(anc), ah_ = __ldg(anc + 1);
        bi = fminf(gw, aw_) * fminf(gl, ah_);
        bd = (area + aw_ * ah_) - bi;
    }
    #pragma unroll
    for (int i = 1; i < NANC; i++) {
        float aw_ = __ldg(anc + 2 * i), ah_ = __ldg(anc + 2 * i + 1);
        float ii = fminf(gw, aw_) * fminf(gl, ah_);
        float di = (area + aw_ * ah_) - ii;
        if (ii * bd > bi * di) { bi = ii; bd = di; bn = i; }
    }
    return bn;
}

// -------------------- the one kernel ----------------------------------------
// grid = (36, 16), block = 320, 4 cells/thread as 2 half2 units
__global__ void __launch_bounds__(NTHR, 4)
k_all(const float* __restrict__ out, const float* __restrict__ tgt,
      const float* __restrict__ anc, float* __restrict__ o, int n) {
    const int b     = blockIdx.y;
    const int blk   = blockIdx.x;
    const int tid   = threadIdx.x;
    const int lane  = tid & 31;
    const int warp  = tid >> 5;
    const int cell0 = blk * CELLS_PER_BLK;

    __shared__ __align__(16) uint s_bp[NT][8];  // {xlo2,xhi2,ylo2,yhi2,mth2,...}
    __shared__ int           s_idx[NT];
    __shared__ unsigned char s_flags[NT];       // bit0 valid, bit1 winner(in-window)
    __shared__ __align__(16) uint s_matchw[CELLS_PER_BLK / 4];  // 320 words
    __shared__ int           s_cnt[2];
    __shared__ float         s_redf[NWARPS];
    __shared__ int           s_last;

    // ---- main per-cell global loads first (longest latency, overlap prep) ----
    const int u   = cell0 + tid * 4;           // 4-cell group, never crosses a row
    const int a   = u / HW;
    const int rem = u - a * HW;
    const int h   = rem / NW;
    const int w0  = rem - h * NW;
    const float* base = out + (size_t)(b * 75 + a * 15) * HW + rem;

    const float4 xr  = *(const float4*)(base);
    const float4 yr  = *(const float4*)(base + HW);
    const float4 wr  = *(const float4*)(base + 2 * HW);
    const float4 lr  = *(const float4*)(base + 3 * HW);
    const float4 cfr = *(const float4*)(base + 6 * HW);

    // ---- zero match map / counters (no target staging pass) -------------------
    s_matchw[tid] = 0u;
    if (tid < 2) s_cnt[tid] = 0;

    // ---- prep (warps 0-1): direct-LDG targets, two-ballot validity ------------
    if (warp < 2) {
        float v0 = __ldg(tgt + (b * NT + lane) * 7 + 1);
        uint mA = __ballot_sync(0xffffffffu, v0 != 0.0f);
        uint mB = 0u;
        if (warp == 1) {
            int t2 = 32 + lane;
            float v1 = (t2 < NT) ? __ldg(tgt + (b * NT + t2) * 7 + 1) : 1.0f;
            mB = __ballot_sync(0xffffffffu, v1 != 0.0f);
        }
        const int t = warp * 32 + lane;
        if (t < NT) {
            bool valid;
            if (warp == 0) valid = (((~mA) & ((2u << lane) - 1u)) == 0u);
            else           valid = (mA == 0xffffffffu) &&
                                   (((~mB) & ((2u << lane) - 1u)) == 0u);

            const float* tp = tgt + (b * NT + t) * 7;
            float gx = __ldg(tp + 1) * (float)NW;
            float gy = __ldg(tp + 2) * (float)NH;
            float gw = __ldg(tp + 3) * (float)NW;
            float gl = __ldg(tp + 4) * (float)NH;

            int bn = best_anchor(gw, gl, anc);
            int gi = min(max((int)gx, 0), NW - 1);
            int gj = min(max((int)gy, 0), NH - 1);
            int idxl = (bn * NH + gj) * NW + gi;

            if (valid) {
                s_idx[t] = idxl;
                s_bp[t][0] = h2u(__float2half2_rn(gx - 0.5f * gw));
                s_bp[t][1] = h2u(__float2half2_rn(gx + 0.5f * gw));
                s_bp[t][2] = h2u(__float2half2_rn(gy - 0.5f * gl));
                s_bp[t][3] = h2u(__float2half2_rn(gy + 0.5f * gl));
                s_bp[t][4] = h2u(__float2half2_rn(-THRESH_Q * gw * gl));
                s_flags[t] = 1u;
            } else {
                s_idx[t] = -2 - t;
                // sentinel: cw clamps to 0, ch FINITE (no 0*inf NaN), mth huge-neg
                s_bp[t][0] = h2u(__float2half2_rn( 60000.f));
                s_bp[t][1] = h2u(__float2half2_rn(-60000.f));
                s_bp[t][2] = h2u(__float2half2_rn(0.f));
                s_bp[t][3] = h2u(__float2half2_rn(0.f));
                s_bp[t][4] = h2u(__float2half2_rn(-60000.f));
                s_flags[t] = 0u;
            }
        }
    }
    __syncthreads();   // barrier 1: boxes/idx/flags + matchw-zero complete

    // ---- winner + match-map write + phase-C L1 prefetch ------------------------
    if (tid < NT && (s_flags[tid] & 1u)) {
        int idxl = s_idx[tid];
        if (idxl >= cell0 && idxl < cell0 + CELLS_PER_BLK) {
            bool winner = true;
            for (int t2 = tid + 1; t2 < NT; t2++)
                if (s_idx[t2] == idxl) winner = false;
            if (winner) {
                s_flags[tid] = 3u;
                ((unsigned char*)s_matchw)[idxl - cell0] = (unsigned char)(tid + 1);
            }
            int bn = idxl / HW;
            int r2 = idxl - bn * HW;
            const float* cbp = out + (size_t)(b * 75 + bn * 15) * HW + r2;
            #pragma unroll
            for (int c = 0; c < 15; c++)
                asm volatile("prefetch.global.L1 [%0];" :: "l"(cbp + c * HW));
        }
    }

    // ---- per-cell geometry (overlaps winner pass for non-prep threads) ---------
    const float X[4] = {xr.x, xr.y, xr.z, xr.w};
    const float Y[4] = {yr.x, yr.y, yr.z, yr.w};
    const float W[4] = {wr.x, wr.y, wr.z, wr.w};
    const float L[4] = {lr.x, lr.y, lr.z, lr.w};

    const float caw = __ldg(anc + 2 * a);
    const float cah = __ldg(anc + 2 * a + 1);

    __half2 xlo2[2], xhi2[2], ylo2[2], yhi2[2], accE[2], accO[2];
    float nap[4];
    #pragma unroll
    for (int i = 0; i < 2; i++) {
        float xl[2], xh[2], yl[2], yh[2];
        #pragma unroll
        for (int k = 0; k < 2; k++) {
            int c = 2 * i + k;
            float sx  = sig_fast(X[c]);
            float sy  = sig_fast(Y[c]);
            float pw  = __expf(W[c]) * caw;
            float pl  = __expf(L[c]) * cah;
            float px  = sx + (float)(w0 + c);
            float py  = sy + (float)h;
            xl[k] = px - 0.5f * pw;  xh[k] = px + 0.5f * pw;
            yl[k] = py - 0.5f * pl;  yh[k] = py + 0.5f * pl;
            nap[c] = -THRESH_Q * pw * pl;
        }
        xlo2[i] = __floats2half2_rn(xl[0], xl[1]);
        xhi2[i] = __floats2half2_rn(xh[0], xh[1]);
        ylo2[i] = __floats2half2_rn(yl[0], yl[1]);
        yhi2[i] = __floats2half2_rn(yh[0], yh[1]);
        accE[i] = __float2half2_rn(-60000.f);
        accO[i] = accE[i];
    }
    const __half2 z2 = __float2half2_rn(0.f);

    __syncthreads();   // barrier 2: match map final

    // ---- main IoU loop: 9 half2 ops per unit per target, even/odd acc ----------
    #pragma unroll 10
    for (int t = 0; t < NT; t += 2) {
        {
            const uint4 q = *(const uint4*)&s_bp[t][0];
            const __half2 Bxlo = u2h(q.x), Bxhi = u2h(q.y);
            const __half2 Bylo = u2h(q.z), Byhi = u2h(q.w);
            const __half2 Bmth = u2h(s_bp[t][4]);
            #pragma unroll
            for (int i = 0; i < 2; i++) {
                __half2 cw = __hmax2(__hsub2(__hmin2(xhi2[i], Bxhi),
                                             __hmax2(xlo2[i], Bxlo)), z2);
                __half2 ch = __hsub2(__hmin2(yhi2[i], Byhi),
                                     __hmax2(ylo2[i], Bylo));
                accE[i] = __hmax2(accE[i], __hfma2(cw, ch, Bmth));
            }
        }
        {
            const uint4 q = *(const uint4*)&s_bp[t + 1][0];
            const __half2 Bxlo = u2h(q.x), Bxhi = u2h(q.y);
            const __half2 Bylo = u2h(q.z), Byhi = u2h(q.w);
            const __half2 Bmth = u2h(s_bp[t + 1][4]);
            #pragma unroll
            for (int i = 0; i < 2; i++) {
                __half2 cw = __hmax2(__hsub2(__hmin2(xhi2[i], Bxhi),
                                             __hmax2(xlo2[i], Bxlo)), z2);
                __half2 ch = __hsub2(__hmin2(yhi2[i], Byhi),
                                     __hmax2(ylo2[i], Bylo));
                accO[i] = __hmax2(accO[i], __hfma2(cw, ch, Bmth));
            }
        }
    }

    bool F[4];
    #pragma unroll
    for (int i = 0; i < 2; i++) {
        __half2 acc = __hmax2(accE[i], accO[i]);
        F[2 * i]     = __low2float(acc)  + nap[2 * i]     > 0.0f;
        F[2 * i + 1] = __high2float(acc) + nap[2 * i + 1] > 0.0f;
    }

    // ---- no-obj conf terms (matched cells handled in phase C) ------------------
    const uint mkw = s_matchw[tid];
    const float CF[4] = {cfr.x, cfr.y, cfr.z, cfr.w};

    float part = 0.0f;
    #pragma unroll
    for (int c = 0; c < 4; c++) {
        uint mk = (mkw >> (8 * c)) & 0xffu;
        if (mk == 0u && !F[c]) {
            float cf = sig_fast(CF[c]);
            part += cf * cf;
        }
    }

    // ---- phase C: targets owned by this block (exact fp32 reference math) ------
    if (tid < NT && (s_flags[tid] & 1u)) {
        int idxl = s_idx[tid];
        if (idxl >= cell0 && idxl < cell0 + CELLS_PER_BLK) {
            const float* tp = tgt + (b * NT + tid) * 7;
            float gx = __ldg(tp + 1) * (float)NW;
            float gy = __ldg(tp + 2) * (float)NH;
            float gw = __ldg(tp + 3) * (float)NW;
            float gl = __ldg(tp + 4) * (float)NH;

            int bn = best_anchor(gw, gl, anc);   // same decision as prep
            float aw_ = __ldg(anc + 2 * bn);
            float ah_ = __ldg(anc + 2 * bn + 1);
            int gi = min(max((int)gx, 0), NW - 1);
            int gj = min(max((int)gy, 0), NH - 1);

            const float* cb = out + (size_t)(b * 75 + bn * 15) * HW + (size_t)gj * NW + gi;
            float xr0 = cb[0], yr0 = cb[HW], wr0 = cb[2 * HW], lr0 = cb[3 * HW];
            float sx = sig_acc(xr0);
            float sy = sig_acc(yr0);
            float px = sx + (float)gi;
            float py = sy + (float)gj;
            float pw = expf(wr0) * aw_;
            float pl = expf(lr0) * ah_;

            float mx = fminf(px - pw * 0.5f, gx - gw * 0.5f);
            float Mx = fmaxf(px + pw * 0.5f, gx + gw * 0.5f);
            float my = fminf(py - pl * 0.5f, gy - gl * 0.5f);
            float My = fmaxf(py + pl * 0.5f, gy + gl * 0.5f);
            float cw = (pw + gw) - (Mx - mx);
            float ch = (pl + gl) - (My - my);
            float inter = ((cw > 0.f) && (ch > 0.f)) ? (cw * ch) : 0.0f;
            float iou = inter / ((pw * pl + gw * gl) - inter);

            atomicAdd(&s_cnt[0], 1);
            if (iou > 0.5f) atomicAdd(&s_cnt[1], 1);

            if (s_flags[tid] & 2u) {   // winner
                float dx = sx - (gx - (float)gi);
                float dy = sy - (gy - (float)gj);
                float dw = wr0 - logf(gw / aw_);
                float dl = lr0 - logf(gl / ah_);
                float di = cb[4 * HW] - __ldg(tp + 5);
                float dr = cb[5 * HW] - __ldg(tp + 6);
                float cf = sig_acc(cb[6 * HW]);
                float dc = cf - iou;

                float lg[NCL];
                #pragma unroll
                for (int c = 0; c < NCL; c++) lg[c] = cb[(7 + c) * HW];
                float m2 = lg[0];
                #pragma unroll
                for (int c = 1; c < NCL; c++) m2 = fmaxf(m2, lg[c]);
                float s = 0.f;
                #pragma unroll
                for (int c = 0; c < NCL; c++) s += expf(lg[c] - m2);
                int tcls = (int)__ldg(tp + 0);
                float ce = (m2 + logf(s)) - lg[tcls];

                part += dx * dx + dy * dy + dw * dw + dl * dl + di * di + dr * dr
                      + 100.0f * dc * dc + ce;
            }
        }
    }

    // ---- block reduction + atomic accumulate -------------------------------------
    #pragma unroll
    for (int off = 16; off > 0; off >>= 1)
        part += __shfl_down_sync(0xffffffffu, part, off);
    if (lane == 0) s_redf[warp] = part;
    __syncthreads();

    if (tid == 0) {
        float v = 0.f;
        #pragma unroll
        for (int wv = 0; wv < NWARPS; wv++) v += s_redf[wv];
        atomicAdd(&g_accF, v);
        if (s_cnt[0]) {
            atomicAdd(&g_accGT, s_cnt[0]);
            if (s_cnt[1]) atomicAdd(&g_accCC, s_cnt[1]);
        }
        __threadfence();
        int old = atomicAdd(&g_ticket, 1);
        s_last = (((old + 1) % NBLK) == 0) ? 1 : 0;
    }
    __syncthreads();

    // ---- last block finalizes: copy 3 scalars, reset accumulators ----------------
    if (s_last) {
        if (tid == 0) {
            float lv = __ldcg(&g_accF);
            int   gt = __ldcg(&g_accGT);
            int   cc = __ldcg(&g_accCC);
            if (n > 0) o[0] = lv;
            if (n > 1) o[1] = (float)cc;
            if (n > 2) o[2] = (float)gt;
            g_accF  = 0.0f;      // reset for next (replayed) launch
            g_accGT = 0;
            g_accCC = 0;
            __threadfence();
        }
        for (int k = 3 + tid; k < n; k += NTHR) o[k] = 0.0f;
    }
}

// -------------------- launch --------------------------------------------------
extern "C" void kernel_launch(void* const* d_in, const int* in_sizes, int n_in,
                              void* d_out, int out_size) {
    const float* output  = (const float*)d_in[0];
    const float* target  = (const float*)d_in[1];
    const float* anchors = (const float*)d_in[2];

    k_all<<<dim3(BLKS_PER_B, NB), NTHR>>>(output, target, anchors,
                                          (float*)d_out, out_size);
}